// round 17
// baseline (speedup 1.0000x reference)
#include <cuda_runtime.h>
#include <cuda_fp16.h>
#include <cstdint>

#define BB 4
#define CC 384
#define QQ 384
#define HH 256
#define KK 256

#define ST 40                 // smem row stride in halves (80B)
#define NTILES (BB*CC*3)      // 4608 q-tiles of 128

// ---------------------------------------------------------------- scratch
__device__ float g_term_h[BB*CC*KK];                 // term_h + b1
__device__ float g_term_u[BB*QQ*KK];                 // term_u
__device__ __align__(16) __half g_whu_h[KK*HH];      // W_hu fp16, [k][h] dense

__device__ __forceinline__ float lrelu(float x) {
    return fmaxf(x, 0.f) + 0.01f * fminf(x, 0.f);
}
__device__ __forceinline__ void mma16(float* d, const uint32_t* a, uint32_t b0, uint32_t b1) {
    asm volatile("mma.sync.aligned.m16n8k16.row.col.f32.f16.f16.f32 "
                 "{%0,%1,%2,%3}, {%4,%5,%6,%7}, {%8,%9}, {%0,%1,%2,%3};"
                 : "+f"(d[0]), "+f"(d[1]), "+f"(d[2]), "+f"(d[3])
                 : "r"(a[0]), "r"(a[1]), "r"(a[2]), "r"(a[3]), "r"(b0), "r"(b1));
}
__device__ __forceinline__ uint32_t smem_u32(const void* p) {
    uint32_t a;
    asm("{ .reg .u64 t; cvta.to.shared.u64 t, %1; cvt.u32.u64 %0, t; }" : "=r"(a) : "l"(p));
    return a;
}
#define CP_ASYNC16(dst, src) \
    asm volatile("cp.async.cg.shared.global [%0], [%1], 16;" :: "r"(dst), "l"(src))
#define CP_COMMIT() asm volatile("cp.async.commit_group;" ::: "memory")
#define CP_WAIT0()  asm volatile("cp.async.wait_group 0;"  ::: "memory")
#define BAR_Q(id) asm volatile("bar.sync %0, 128;" :: "r"(id) : "memory")

__device__ __forceinline__ uint2 pack_h4(float4 v) {
    __half2 p0 = __floats2half2_rn(v.x, v.y);
    __half2 p1 = __floats2half2_rn(v.z, v.w);
    return make_uint2(*reinterpret_cast<uint32_t*>(&p0), *reinterpret_cast<uint32_t*>(&p1));
}

// ---------------------------------------------------------------- tensor-core prep kernel
// (R16 configuration. UNCHANGED.)
__global__ __launch_bounds__(256)
void prep_mma_kernel(const float* __restrict__ h, const float* __restrict__ u,
                     const float* __restrict__ w1, const float* __restrict__ b1) {
    const int blk = blockIdx.x;
    const int tid = threadIdx.x;

    if (blk >= 48) {   // ---- pack W_hu ----
        const int k0 = (blk - 48) * 4;
        #pragma unroll
        for (int r = 0; r < 4; r++)
            g_whu_h[(k0 + r) * HH + tid] =
                __float2half_rn(w1[(size_t)(k0 + r) * (3 * HH) + 2 * HH + tid]);
        return;
    }

    __shared__ __half As_[64 * ST];
    __shared__ __half Bs_[256 * ST];

    const bool is_h = blk < 24;
    const int r0 = (is_h ? blk : blk - 24) * 64;
    const float* x = is_h ? h : u;
    float* outb = is_h ? g_term_h : g_term_u;
    const int coloff = is_h ? 0 : HH;

    const int lid = tid & 31;
    const int wid = tid >> 5;
    const int g   = lid >> 2;
    const int t   = lid & 3;
    const int warpM = wid >> 2;
    const int warpN = wid & 3;

    float acc[2][8][4];
    #pragma unroll
    for (int mt = 0; mt < 2; mt++)
        #pragma unroll
        for (int nt = 0; nt < 8; nt++)
            #pragma unroll
            for (int e = 0; e < 4; e++) acc[mt][nt][e] = 0.f;

    const int ar = tid >> 3, ac4 = tid & 7;
    const int ar2 = (tid + 256) >> 3;
    float4 aR[2], bR[8];

    auto load_regs = [&](int ch) {
        aR[0] = *reinterpret_cast<const float4*>(x + (size_t)(r0 + ar) * HH + ch * 32 + ac4 * 4);
        aR[1] = *reinterpret_cast<const float4*>(x + (size_t)(r0 + ar2) * HH + ch * 32 + ac4 * 4);
        #pragma unroll
        for (int i = 0; i < 8; i++) {
            const int idx = tid + i * 256;
            const int row = idx >> 3, c4 = idx & 7;
            bR[i] = *reinterpret_cast<const float4*>(
                w1 + (size_t)row * (3 * HH) + coloff + ch * 32 + c4 * 4);
        }
    };
    auto store_regs = [&]() {
        *reinterpret_cast<uint2*>(&As_[ar  * ST + ac4 * 4]) = pack_h4(aR[0]);
        *reinterpret_cast<uint2*>(&As_[ar2 * ST + ac4 * 4]) = pack_h4(aR[1]);
        #pragma unroll
        for (int i = 0; i < 8; i++) {
            const int idx = tid + i * 256;
            const int row = idx >> 3, c4 = idx & 7;
            *reinterpret_cast<uint2*>(&Bs_[row * ST + c4 * 4]) = pack_h4(bR[i]);
        }
    };

    load_regs(0);
    store_regs();
    __syncthreads();

    for (int ch = 0; ch < 8; ch++) {
        if (ch < 7) load_regs(ch + 1);

        const uint32_t* Asu = reinterpret_cast<const uint32_t*>(As_);
        const uint32_t* Bsu = reinterpret_cast<const uint32_t*>(Bs_);
        #pragma unroll
        for (int s = 0; s < 2; s++) {
            const int k2 = s * 8;
            uint32_t af[2][4];
            #pragma unroll
            for (int mt = 0; mt < 2; mt++) {
                const int r0i = (warpM * 32 + mt * 16 + g) * (ST / 2) + k2 + t;
                af[mt][0] = Asu[r0i];
                af[mt][1] = Asu[r0i + 8 * (ST / 2)];
                af[mt][2] = Asu[r0i + 4];
                af[mt][3] = Asu[r0i + 8 * (ST / 2) + 4];
            }
            #pragma unroll
            for (int nt = 0; nt < 8; nt++) {
                const int nb = (warpN * 64 + nt * 8 + g) * (ST / 2) + k2 + t;
                const uint32_t b0 = Bsu[nb];
                const uint32_t b1r = Bsu[nb + 4];
                #pragma unroll
                for (int mt = 0; mt < 2; mt++)
                    mma16(acc[mt][nt], af[mt], b0, b1r);
            }
        }
        __syncthreads();
        if (ch < 7) {
            store_regs();
            __syncthreads();
        }
    }

    #pragma unroll
    for (int nt = 0; nt < 8; nt++) {
        const int k = warpN * 64 + nt * 8 + 2 * t;
        float2 bv = is_h ? *reinterpret_cast<const float2*>(b1 + k)
                         : make_float2(0.f, 0.f);
        #pragma unroll
        for (int mt = 0; mt < 2; mt++)
            #pragma unroll
            for (int half = 0; half < 2; half++) {
                const int row = warpM * 32 + mt * 16 + half * 8 + g;
                float2 v = make_float2(acc[mt][nt][half * 2 + 0] + bv.x,
                                       acc[mt][nt][half * 2 + 1] + bv.y);
                *reinterpret_cast<float2*>(outb + (size_t)(r0 + row) * KK + k) = v;
            }
    }
}

// ---------------------------------------------------------------- persistent main kernel
// 512 threads / 16 warps = 4M x 4N; each quarter (warpM) owns 32 A-rows and
// syncs with bar.sync 1+warpM over 128 threads. B resident; meta double-buffered;
// balanced tiles + tail half-tiles.
#define BSP    0
#define BCHUNK 20480                  // 256*ST*2 bytes per K-chunk of B
#define AS0    (BSP + 8*BCHUNK)       // 163840
#define AS1    (AS0 + 10240)          // 174080
#define RED    (AS1 + 10240)          // 184320
#define HC0    (RED + 2048)           // 186368
#define HC1    (HC0 + 1024)
#define TH0    (HC1 + 1024)
#define TH1    (TH0 + 1024)
#define W2O    (TH1 + 1024)
#define SMEM_BYTES (W2O + 1024)       // 191488

__global__ __launch_bounds__(512, 1)
void main_mma_kernel(const float* __restrict__ hmat,
                     const float* __restrict__ u,
                     const float* __restrict__ w2v,
                     const float* __restrict__ b2,
                     float* __restrict__ out)
{
    extern __shared__ char sm[];
    __half* As[2] = { reinterpret_cast<__half*>(sm + AS0), reinterpret_cast<__half*>(sm + AS1) };
    float* red    = reinterpret_cast<float*>(sm + RED);
    float* hcb[2] = { reinterpret_cast<float*>(sm + HC0), reinterpret_cast<float*>(sm + HC1) };
    float* thb[2] = { reinterpret_cast<float*>(sm + TH0), reinterpret_cast<float*>(sm + TH1) };
    float* w2_s   = reinterpret_cast<float*>(sm + W2O);

    const int tid = threadIdx.x;
    const int lid = tid & 31;
    const int wid = tid >> 5;
    const int g   = lid >> 2;
    const int t   = lid & 3;
    const int warpM = wid >> 2;      // 0..3 (quarter; 32 q-rows each)
    const int warpN = wid & 3;       // 0..3 (64 k-cols each)
    const int ht  = tid & 127;       // thread-in-quarter
    const int barid = 1 + warpM;

    const int G     = gridDim.x;
    const int NPER  = NTILES / G;
    const int NFULL = NPER * G;
    const int NREM2 = 2 * (NTILES - NFULL);

    const uint32_t smb = smem_u32(sm);

    // ---- one-time prologue: fill resident B (8 chunks) ----
    {
        const int br[2] = { tid >> 2, (tid + 512) >> 2 };
        const int bs = tid & 3;
        #pragma unroll
        for (int ch = 0; ch < 8; ch++)
            #pragma unroll
            for (int i = 0; i < 2; i++)
                CP_ASYNC16(smb + BSP + ch * BCHUNK + br[i] * (ST * 2) + bs * 16,
                           g_whu_h + (size_t)br[i] * HH + ch * 32 + bs * 8);
        CP_COMMIT();
    }
    // ---- first tile meta + w2 ----
    {
        const int bc0 = blockIdx.x / 3;
        if (tid < 64)
            CP_ASYNC16(smb + HC0 + tid * 16, hmat + (size_t)bc0 * HH + tid * 4);
        else if (tid < 128)
            CP_ASYNC16(smb + TH0 + (tid - 64) * 16, g_term_h + (size_t)bc0 * KK + (tid - 64) * 4);
        else if (tid < 192)
            CP_ASYNC16(smb + W2O + (tid - 128) * 16, w2v + (tid - 128) * 4);
        CP_COMMIT();
    }
    CP_WAIT0();
    __syncthreads();
    const float b2v = b2[0];

    // A-load coords: quarter owns rows [warpM*32, warpM*32+32); 256 segs over 128 thr
    const int arow[2] = { warpM * 32 + (ht >> 3),
                          warpM * 32 + ((ht + 128) >> 3) };
    const int ac4 = ht & 7;

    int par = 0;
    for (int w = 0; w < NPER; w++) {
        const int tile = blockIdx.x + w * G;
        const int bc = tile / 3;
        const int qt = tile - bc * 3;
        const int b  = bc / CC;
        const int q0 = qt * 128;
        const float* u_base = u + (size_t)(b * QQ + q0) * HH;
        const float* h_c  = hcb[par];
        const float* th_s = thb[par];

        float acc[2][8][4];
        #pragma unroll
        for (int mt = 0; mt < 2; mt++)
            #pragma unroll
            for (int nt = 0; nt < 8; nt++)
                #pragma unroll
                for (int e = 0; e < 4; e++) acc[mt][nt][e] = 0.f;

        auto load_A = [&](int ch, float4* aN) {
            #pragma unroll
            for (int i = 0; i < 2; i++)
                aN[i] = *reinterpret_cast<const float4*>(
                    u_base + (size_t)arow[i] * HH + ch * 32 + ac4 * 4);
        };
        auto scale_store_A = [&](int ch, float4* aN, int buf) {
            const int kb = ac4 * 4;
            float4 hv = *reinterpret_cast<const float4*>(&h_c[ch * 32 + kb]);
            #pragma unroll
            for (int i = 0; i < 2; i++) {
                float4 v = make_float4(aN[i].x * hv.x, aN[i].y * hv.y,
                                       aN[i].z * hv.z, aN[i].w * hv.w);
                *reinterpret_cast<uint2*>(&As[buf][arow[i] * ST + kb]) = pack_h4(v);
            }
        };

        // chunk 0 + next meta prefetch
        {
            float4 aN[2];
            load_A(0, aN);
            int nbc = -1;
            if (w < NPER - 1)               nbc = (tile + G) / 3;
            else if (blockIdx.x < NREM2)    nbc = (NFULL + (blockIdx.x >> 1)) / 3;
            if (nbc >= 0) {
                const uint32_t hdst = (par ? HC0 : HC1);
                const uint32_t tdst = (par ? TH0 : TH1);
                if (tid < 64)
                    CP_ASYNC16(smb + hdst + tid * 16, hmat + (size_t)nbc * HH + tid * 4);
                else if (tid < 128)
                    CP_ASYNC16(smb + tdst + (tid - 64) * 16,
                               g_term_h + (size_t)nbc * KK + (tid - 64) * 4);
                CP_COMMIT();
            }
            scale_store_A(0, aN, 0);
            BAR_Q(barid);
        }

        for (int ch = 0; ch < 8; ch++) {
            float4 aN[2];
            if (ch < 7) load_A(ch + 1, aN);

            const uint32_t* Asu = reinterpret_cast<const uint32_t*>(As[ch & 1]);
            const uint32_t* Bsu = reinterpret_cast<const uint32_t*>(sm + BSP + ch * BCHUNK);
            #pragma unroll
            for (int s = 0; s < 2; s++) {
                const int k2 = s * 8;
                uint32_t af[2][4];
                #pragma unroll
                for (int mt = 0; mt < 2; mt++) {
                    const int r0i = (warpM * 32 + mt * 16 + g) * (ST / 2) + k2 + t;
                    af[mt][0] = Asu[r0i];
                    af[mt][1] = Asu[r0i + 8 * (ST / 2)];
                    af[mt][2] = Asu[r0i + 4];
                    af[mt][3] = Asu[r0i + 8 * (ST / 2) + 4];
                }
                #pragma unroll
                for (int nt = 0; nt < 8; nt++) {
                    const int nb = (warpN * 64 + nt * 8 + g) * (ST / 2) + k2 + t;
                    const uint32_t b0 = Bsu[nb];
                    const uint32_t b1 = Bsu[nb + 4];
                    #pragma unroll
                    for (int mt = 0; mt < 2; mt++)
                        mma16(acc[mt][nt], af[mt], b0, b1);
                }
            }

            if (ch < 7) scale_store_A(ch + 1, aN, (ch + 1) & 1);
            BAR_Q(barid);
        }

        // ---- epilogue ----
        #pragma unroll
        for (int mt = 0; mt < 2; mt++) {
            #pragma unroll
            for (int half = 0; half < 2; half++) {
                const int row = warpM * 32 + mt * 16 + half * 8 + g;
                const int q = q0 + row;
                const float* tu = g_term_u + (size_t)(b * QQ + q) * KK;
                float s = 0.f;
                #pragma unroll
                for (int nt = 0; nt < 8; nt++) {
                    const int k = warpN * 64 + nt * 8 + 2 * t;
                    float2 tv = *reinterpret_cast<const float2*>(tu + k);
                    float v0 = acc[mt][nt][half * 2 + 0] + th_s[k]     + tv.x;
                    float v1 = acc[mt][nt][half * 2 + 1] + th_s[k + 1] + tv.y;
                    s += w2_s[k]     * lrelu(v0);
                    s += w2_s[k + 1] * lrelu(v1);
                }
                s += __shfl_xor_sync(0xffffffffu, s, 1);
                s += __shfl_xor_sync(0xffffffffu, s, 2);
                if (t == 0) red[warpN * 128 + row] = s;
            }
        }
        CP_WAIT0();
        __syncthreads();
        if (tid < 128) {
            float s = red[tid] + red[128 + tid] + red[256 + tid] + red[384 + tid] + b2v;
            out[(size_t)bc * QQ + q0 + tid] = lrelu(s);
        }
        par ^= 1;
    }

    // ---- remainder: one half-tile (M=64) for CTAs [0, NREM2) ----
    if (blockIdx.x < NREM2) {
        const int tile = NFULL + (blockIdx.x >> 1);
        const int m0 = (blockIdx.x & 1) * 64;
        const int bc = tile / 3;
        const int qt = tile - bc * 3;
        const int b  = bc / CC;
        const int q0 = qt * 128 + m0;
        const float* u_base = u + (size_t)(b * QQ + q0) * HH;
        const float* h_c  = hcb[par];
        const float* th_s = thb[par];

        // 64 rows: warp tile 16x64 (4M x 4N). A: 512 segs over 512 threads.
        const int arow2 = tid >> 3;
        const int ac42 = tid & 7;

        float acc[8][4];
        #pragma unroll
        for (int nt = 0; nt < 8; nt++)
            #pragma unroll
            for (int e = 0; e < 4; e++) acc[nt][e] = 0.f;

        auto load_A2 = [&](int ch, float4* aN) {
            aN[0] = *reinterpret_cast<const float4*>(
                u_base + (size_t)arow2 * HH + ch * 32 + ac42 * 4);
        };
        auto scale_store_A2 = [&](int ch, float4* aN, int buf) {
            const int kb = ac42 * 4;
            float4 hv = *reinterpret_cast<const float4*>(&h_c[ch * 32 + kb]);
            float4 v = make_float4(aN[0].x * hv.x, aN[0].y * hv.y,
                                   aN[0].z * hv.z, aN[0].w * hv.w);
            *reinterpret_cast<uint2*>(&As[buf][arow2 * ST + kb]) = pack_h4(v);
        };

        {
            float4 aN[1];
            load_A2(0, aN);
            scale_store_A2(0, aN, 0);
            __syncthreads();
        }

        for (int ch = 0; ch < 8; ch++) {
            float4 aN[1];
            if (ch < 7) load_A2(ch + 1, aN);

            const uint32_t* Asu = reinterpret_cast<const uint32_t*>(As[ch & 1]);
            const uint32_t* Bsu = reinterpret_cast<const uint32_t*>(sm + BSP + ch * BCHUNK);
            #pragma unroll
            for (int s = 0; s < 2; s++) {
                const int k2 = s * 8;
                uint32_t af[4];
                {
                    const int r0i = (warpM * 16 + g) * (ST / 2) + k2 + t;
                    af[0] = Asu[r0i];
                    af[1] = Asu[r0i + 8 * (ST / 2)];
                    af[2] = Asu[r0i + 4];
                    af[3] = Asu[r0i + 8 * (ST / 2) + 4];
                }
                #pragma unroll
                for (int nt = 0; nt < 8; nt++) {
                    const int nb = (warpN * 64 + nt * 8 + g) * (ST / 2) + k2 + t;
                    const uint32_t b0 = Bsu[nb];
                    const uint32_t b1 = Bsu[nb + 4];
                    mma16(acc[nt], af, b0, b1);
                }
            }

            if (ch < 7) scale_store_A2(ch + 1, aN, (ch + 1) & 1);
            __syncthreads();
        }

        #pragma unroll
        for (int half = 0; half < 2; half++) {
            const int row = warpM * 16 + half * 8 + g;
            const int q = q0 + row;
            const float* tu = g_term_u + (size_t)(b * QQ + q) * KK;
            float s = 0.f;
            #pragma unroll
            for (int nt = 0; nt < 8; nt++) {
                const int k = warpN * 64 + nt * 8 + 2 * t;
                float2 tv = *reinterpret_cast<const float2*>(tu + k);
                float v0 = acc[nt][half * 2 + 0] + th_s[k]     + tv.x;
                float v1 = acc[nt][half * 2 + 1] + th_s[k + 1] + tv.y;
                s += w2_s[k]     * lrelu(v0);
                s += w2_s[k + 1] * lrelu(v1);
            }
            s += __shfl_xor_sync(0xffffffffu, s, 1);
            s += __shfl_xor_sync(0xffffffffu, s, 2);
            if (t == 0) red[warpN * 64 + row] = s;
        }
        __syncthreads();
        if (tid < 64) {
            float s = red[tid] + red[64 + tid] + red[128 + tid] + red[192 + tid] + b2v;
            out[(size_t)bc * QQ + q0 + tid] = lrelu(s);
        }
    }
}

// ---------------------------------------------------------------- launch
extern "C" void kernel_launch(void* const* d_in, const int* in_sizes, int n_in,
                              void* d_out, int out_size) {
    (void)in_sizes; (void)n_in; (void)out_size;
    const float* h_  = (const float*)d_in[0];
    const float* u_  = (const float*)d_in[1];
    const float* w1_ = (const float*)d_in[2];
    const float* b1_ = (const float*)d_in[3];
    const float* w2_ = (const float*)d_in[4];
    const float* b2_ = (const float*)d_in[5];
    float* out_ = (float*)d_out;

    int dev = 0, nsm = 148;
    cudaGetDevice(&dev);
    cudaDeviceGetAttribute(&nsm, cudaDevAttrMultiProcessorCount, dev);

    cudaFuncSetAttribute(main_mma_kernel,
                         cudaFuncAttributeMaxDynamicSharedMemorySize, SMEM_BYTES);

    prep_mma_kernel<<<112, 256>>>(h_, u_, w1_, b1_);
    main_mma_kernel<<<nsm, 512, SMEM_BYTES>>>(h_, u_, w2_, b2_, out_);
}